// round 6
// baseline (speedup 1.0000x reference)
#include <cuda_runtime.h>
#include <cuda_bf16.h>
#include <cstdint>

#define N_NODES 50000
#define MAX_E   800000
#define MAX_TOT (MAX_E + N_NODES)
#define F1 128
#define F2 64

// ---------------- scratch (no allocations allowed) ----------------
__device__ int   g_cnt[N_NODES];
__device__ int   g_cursor[N_NODES];
__device__ int   g_rowptr[N_NODES + 1];
__device__ int2  g_colnrm[MAX_TOT];      // .x = src col, .y = bitcast(norm)
__device__ float g_dinv[N_NODES];
__device__ float g_H1[(size_t)N_NODES * F1];   // x @ W1
__device__ float g_A1[(size_t)N_NODES * F1];   // relu(agg + b1)
__device__ float g_H2[(size_t)N_NODES * F2];   // A1 @ W2
__device__ int   g_is64;

// ---------------- edge dtype probe + init ----------------
__global__ void k_init_detect(const void* ei) {
    int i = blockIdx.x * blockDim.x + threadIdx.x;
    if (i < N_NODES) { g_cnt[i] = 1; g_cursor[i] = 0; }
    if (i == 0) {
        const long long* p = (const long long*)ei;
        int ok = 1;
        for (int j = 0; j < 64; j++) {
            long long v = p[j];
            if (v < 0 || v >= N_NODES) { ok = 0; break; }
        }
        g_is64 = ok;
    }
}

__device__ __forceinline__ int edge_at(const void* ei, int E, int which, int idx) {
    if (g_is64) return (int)((const long long*)ei)[(size_t)which * E + idx];
    return ((const int*)ei)[(size_t)which * E + idx];
}

__global__ void k_degree(const void* __restrict__ ei, int E) {
    int e = blockIdx.x * blockDim.x + threadIdx.x;
    if (e < E) atomicAdd(&g_cnt[edge_at(ei, E, 1, e)], 1);
}

// ---------------- exclusive scan + dinv (single block) ----------------
__global__ void k_scan() {
    const int T = 1024;
    int t = threadIdx.x;
    const int per = (N_NODES + T - 1) / T;
    int s = t * per;
    int e = min(s + per, N_NODES);
    int local = 0;
    for (int i = s; i < e; i++) local += g_cnt[i];
    __shared__ int sm[T];
    sm[t] = local;
    __syncthreads();
    for (int off = 1; off < T; off <<= 1) {
        int v = (t >= off) ? sm[t - off] : 0;
        __syncthreads();
        sm[t] += v;
        __syncthreads();
    }
    int run = sm[t] - local;
    for (int i = s; i < e; i++) {
        int c = g_cnt[i];
        g_rowptr[i] = run;
        run += c;
        g_dinv[i] = rsqrtf((float)c);
    }
    if (t == T - 1) g_rowptr[N_NODES] = sm[T - 1];
}

// ---------------- CSR scatter (edges + self loops), packed 8B stores ----------------
__global__ void k_scatter(const void* __restrict__ ei, int E) {
    int i = blockIdx.x * blockDim.x + threadIdx.x;
    int tot = E + N_NODES;
    if (i >= tot) return;
    int s, d;
    if (i < E) { s = edge_at(ei, E, 0, i); d = edge_at(ei, E, 1, i); }
    else       { s = d = i - E; }
    int pos = g_rowptr[d] + atomicAdd(&g_cursor[d], 1);
    int2 v;
    v.x = s;
    v.y = __float_as_int(g_dinv[s] * g_dinv[d]);
    g_colnrm[pos] = v;
}

// ============ FFMA2 SGEMM: C[M,NOUT] = A[M,128] @ W[128,NOUT] ============
// Round-1 structure (64x64x16 tile, 256 thr, single-buffer) with packed
// fp32x2 FMA: accumulators are (m,m+1) pairs; B duplicated in smem so the
// broadcast pair is a direct LDS.128.
__device__ __forceinline__ unsigned long long fma2(unsigned long long a,
        unsigned long long b, unsigned long long c) {
    unsigned long long d;
    asm("fma.rn.f32x2 %0, %1, %2, %3;" : "=l"(d) : "l"(a), "l"(b), "l"(c));
    return d;
}

template<int NOUT>
__global__ __launch_bounds__(256) void k_sgemm(const float* __restrict__ A,
        const float* __restrict__ W, float* __restrict__ C, int M) {
    const int BM = 64, BN = 64, BK = 16;
    __shared__ float As[BK][BM];          // k-major, m contiguous
    __shared__ float Bsd[BK][BN * 2];     // duplicated: [k][2n]=[k][2n+1]=B[k][n]

    int tid = threadIdx.x;
    int tx = tid & 15, ty = tid >> 4;
    int rowBase = blockIdx.y * BM, colBase = blockIdx.x * BN;
    int aRow = tid >> 2,  aCol = (tid & 3) << 2;
    int bRow = tid >> 4,  bCol = (tid & 15) << 2;

    unsigned long long acc[2][4];
#pragma unroll
    for (int i = 0; i < 2; i++)
#pragma unroll
        for (int j = 0; j < 4; j++) acc[i][j] = 0ull;

    for (int k0 = 0; k0 < 128; k0 += BK) {
        float4 av = make_float4(0.f, 0.f, 0.f, 0.f);
        int gr = rowBase + aRow;
        if (gr < M) av = *(const float4*)(A + (size_t)gr * 128 + k0 + aCol);
        As[aCol + 0][aRow] = av.x;
        As[aCol + 1][aRow] = av.y;
        As[aCol + 2][aRow] = av.z;
        As[aCol + 3][aRow] = av.w;
        float4 bv = *(const float4*)(W + (size_t)(k0 + bRow) * NOUT + colBase + bCol);
        *(float4*)&Bsd[bRow][2 * bCol]     = make_float4(bv.x, bv.x, bv.y, bv.y);
        *(float4*)&Bsd[bRow][2 * bCol + 4] = make_float4(bv.z, bv.z, bv.w, bv.w);
        __syncthreads();
#pragma unroll
        for (int k = 0; k < BK; k++) {
            ulonglong2 a  = *(const ulonglong2*)&As[k][ty << 2];     // (m0,m1),(m2,m3)
            ulonglong2 b0 = *(const ulonglong2*)&Bsd[k][tx << 3];    // dup n0, dup n1
            ulonglong2 b1 = *(const ulonglong2*)&Bsd[k][(tx << 3) + 4]; // dup n2, n3
            acc[0][0] = fma2(a.x, b0.x, acc[0][0]);
            acc[0][1] = fma2(a.x, b0.y, acc[0][1]);
            acc[0][2] = fma2(a.x, b1.x, acc[0][2]);
            acc[0][3] = fma2(a.x, b1.y, acc[0][3]);
            acc[1][0] = fma2(a.y, b0.x, acc[1][0]);
            acc[1][1] = fma2(a.y, b0.y, acc[1][1]);
            acc[1][2] = fma2(a.y, b1.x, acc[1][2]);
            acc[1][3] = fma2(a.y, b1.y, acc[1][3]);
        }
        __syncthreads();
    }

    // ---- epilogue: unpack pairs, 1 float4 store per row ----
#pragma unroll
    for (int i = 0; i < 2; i++) {
#pragma unroll
        for (int h = 0; h < 2; h++) {
            int r = rowBase + (ty << 2) + 2 * i + h;
            if (r < M) {
                float v[4];
#pragma unroll
                for (int j = 0; j < 4; j++) {
                    float2 p = *(float2*)&acc[i][j];
                    v[j] = h ? p.y : p.x;
                }
                *(float4*)(C + (size_t)r * NOUT + colBase + (tx << 2)) =
                    make_float4(v[0], v[1], v[2], v[3]);
            }
        }
    }
}

// ---------------- layer-1 aggregation + bias + relu ----------------
__global__ __launch_bounds__(256) void k_agg1(const float* __restrict__ b1) {
    int warp = (blockIdx.x * blockDim.x + threadIdx.x) >> 5;
    if (warp >= N_NODES) return;
    int lane = threadIdx.x & 31;
    int beg = g_rowptr[warp], end = g_rowptr[warp + 1];
    const int off = lane << 2;
    float4 acc = make_float4(0.f, 0.f, 0.f, 0.f);
    int j = beg;
    for (; j + 4 <= end; j += 4) {
        int2 e0 = g_colnrm[j], e1 = g_colnrm[j + 1];
        int2 e2 = g_colnrm[j + 2], e3 = g_colnrm[j + 3];
        float4 h0 = *(const float4*)(g_H1 + (size_t)e0.x * F1 + off);
        float4 h1 = *(const float4*)(g_H1 + (size_t)e1.x * F1 + off);
        float4 h2 = *(const float4*)(g_H1 + (size_t)e2.x * F1 + off);
        float4 h3 = *(const float4*)(g_H1 + (size_t)e3.x * F1 + off);
        float w0 = __int_as_float(e0.y), w1 = __int_as_float(e1.y);
        float w2 = __int_as_float(e2.y), w3 = __int_as_float(e3.y);
        acc.x = fmaf(h0.x, w0, fmaf(h1.x, w1, fmaf(h2.x, w2, fmaf(h3.x, w3, acc.x))));
        acc.y = fmaf(h0.y, w0, fmaf(h1.y, w1, fmaf(h2.y, w2, fmaf(h3.y, w3, acc.y))));
        acc.z = fmaf(h0.z, w0, fmaf(h1.z, w1, fmaf(h2.z, w2, fmaf(h3.z, w3, acc.z))));
        acc.w = fmaf(h0.w, w0, fmaf(h1.w, w1, fmaf(h2.w, w2, fmaf(h3.w, w3, acc.w))));
    }
    for (; j < end; j++) {
        int2 e0 = g_colnrm[j];
        float w0 = __int_as_float(e0.y);
        float4 h0 = *(const float4*)(g_H1 + (size_t)e0.x * F1 + off);
        acc.x = fmaf(h0.x, w0, acc.x);
        acc.y = fmaf(h0.y, w0, acc.y);
        acc.z = fmaf(h0.z, w0, acc.z);
        acc.w = fmaf(h0.w, w0, acc.w);
    }
    float4 bb = *(const float4*)(b1 + off);
    float4 o;
    o.x = fmaxf(acc.x + bb.x, 0.f);
    o.y = fmaxf(acc.y + bb.y, 0.f);
    o.z = fmaxf(acc.z + bb.z, 0.f);
    o.w = fmaxf(acc.w + bb.w, 0.f);
    *(float4*)(g_A1 + (size_t)warp * F1 + off) = o;
}

// ---------------- layer-2 aggregation + bias + softmax ----------------
__global__ __launch_bounds__(256) void k_agg2(const float* __restrict__ b2,
                                              float* __restrict__ out) {
    int warp = (blockIdx.x * blockDim.x + threadIdx.x) >> 5;
    if (warp >= N_NODES) return;
    int lane = threadIdx.x & 31;
    int beg = g_rowptr[warp], end = g_rowptr[warp + 1];
    const int off = lane << 1;
    float2 acc = make_float2(0.f, 0.f);
    int j = beg;
    for (; j + 4 <= end; j += 4) {
        int2 e0 = g_colnrm[j], e1 = g_colnrm[j + 1];
        int2 e2 = g_colnrm[j + 2], e3 = g_colnrm[j + 3];
        float2 h0 = *(const float2*)(g_H2 + (size_t)e0.x * F2 + off);
        float2 h1 = *(const float2*)(g_H2 + (size_t)e1.x * F2 + off);
        float2 h2 = *(const float2*)(g_H2 + (size_t)e2.x * F2 + off);
        float2 h3 = *(const float2*)(g_H2 + (size_t)e3.x * F2 + off);
        float w0 = __int_as_float(e0.y), w1 = __int_as_float(e1.y);
        float w2 = __int_as_float(e2.y), w3 = __int_as_float(e3.y);
        acc.x = fmaf(h0.x, w0, fmaf(h1.x, w1, fmaf(h2.x, w2, fmaf(h3.x, w3, acc.x))));
        acc.y = fmaf(h0.y, w0, fmaf(h1.y, w1, fmaf(h2.y, w2, fmaf(h3.y, w3, acc.y))));
    }
    for (; j < end; j++) {
        int2 e0 = g_colnrm[j];
        float w0 = __int_as_float(e0.y);
        float2 h0 = *(const float2*)(g_H2 + (size_t)e0.x * F2 + off);
        acc.x = fmaf(h0.x, w0, acc.x);
        acc.y = fmaf(h0.y, w0, acc.y);
    }
    float2 bb = *(const float2*)(b2 + off);
    float l0 = acc.x + bb.x;
    float l1 = acc.y + bb.y;
    float m = fmaxf(l0, l1);
#pragma unroll
    for (int o = 16; o > 0; o >>= 1)
        m = fmaxf(m, __shfl_xor_sync(0xffffffffu, m, o));
    float e0 = __expf(l0 - m);
    float e1 = __expf(l1 - m);
    float s = e0 + e1;
#pragma unroll
    for (int o = 16; o > 0; o >>= 1)
        s += __shfl_xor_sync(0xffffffffu, s, o);
    float inv = 1.0f / s;
    *(float2*)(out + (size_t)warp * F2 + off) = make_float2(e0 * inv, e1 * inv);
}

// ---------------- launch ----------------
extern "C" void kernel_launch(void* const* d_in, const int* in_sizes, int n_in,
                              void* d_out, int out_size) {
    const float* x  = (const float*)d_in[0];
    const void*  ei = d_in[1];
    const float* W1 = (const float*)d_in[2];
    const float* b1 = (const float*)d_in[3];
    const float* W2 = (const float*)d_in[4];
    const float* b2 = (const float*)d_in[5];
    float* out = (float*)d_out;
    int E = in_sizes[1] / 2;

    float *H1, *A1, *H2;
    cudaGetSymbolAddress((void**)&H1, g_H1);
    cudaGetSymbolAddress((void**)&A1, g_A1);
    cudaGetSymbolAddress((void**)&H2, g_H2);

    const int mTiles = (N_NODES + 63) / 64;   // 782

    k_init_detect<<<(N_NODES + 255) / 256, 256>>>(ei);
    k_degree<<<(E + 255) / 256, 256>>>(ei, E);
    k_scan<<<1, 1024>>>();
    k_scatter<<<(E + N_NODES + 255) / 256, 256>>>(ei, E);

    k_sgemm<128><<<dim3(2, mTiles), 256>>>(x, W1, H1, N_NODES);
    k_agg1<<<(N_NODES * 32 + 255) / 256, 256>>>(b1);
    k_sgemm<64><<<dim3(1, mTiles), 256>>>(A1, W2, H2, N_NODES);
    k_agg2<<<(N_NODES * 32 + 255) / 256, 256>>>(b2, out);
}

// round 7
// speedup vs baseline: 1.4073x; 1.4073x over previous
#include <cuda_runtime.h>
#include <cuda_bf16.h>
#include <cstdint>

#define N_NODES 50000
#define MAX_E   800000
#define MAX_TOT (MAX_E + N_NODES)
#define F1 128
#define F2 64

// ---------------- scratch (no allocations allowed) ----------------
__device__ int   g_cnt[N_NODES];
__device__ int   g_cursor[N_NODES];
__device__ int   g_rowptr[N_NODES + 1];
__device__ int2  g_colnrm[MAX_TOT];      // .x = src col, .y = bitcast(norm)
__device__ float g_dinv[N_NODES];
__device__ float g_H1[(size_t)N_NODES * F1];   // x @ W1
__device__ float g_A1[(size_t)N_NODES * F1];   // relu(agg + b1)
__device__ float g_H2[(size_t)N_NODES * F2];   // A1 @ W2
__device__ int   g_is64;

// ---------------- edge dtype probe + init ----------------
__global__ void k_init_detect(const void* ei) {
    int i = blockIdx.x * blockDim.x + threadIdx.x;
    if (i < N_NODES) { g_cnt[i] = 1; g_cursor[i] = 0; }
    if (i == 0) {
        const long long* p = (const long long*)ei;
        int ok = 1;
        for (int j = 0; j < 64; j++) {
            long long v = p[j];
            if (v < 0 || v >= N_NODES) { ok = 0; break; }
        }
        g_is64 = ok;
    }
}

__device__ __forceinline__ int edge_at(const void* ei, int E, int which, int idx) {
    if (g_is64) return (int)((const long long*)ei)[(size_t)which * E + idx];
    return ((const int*)ei)[(size_t)which * E + idx];
}

// ============ round-1 SGEMM tile as device function ============
// C[M,NOUT] = A[M,128] @ W[128,NOUT]; one 64x64 tile per block, 256 threads.
template<int NOUT>
__device__ __forceinline__ void sgemm_tile(const float* __restrict__ A,
        const float* __restrict__ W, float* __restrict__ C, int M, int tile) {
    const int BM = 64, BN = 64, BK = 16;
    const int colTiles = NOUT / 64;
    __shared__ float As[BK][BM];
    __shared__ float Bs[BK][BN];
    int tid = threadIdx.x;
    int tx = tid & 15, ty = tid >> 4;
    int rowBase = (tile / colTiles) * BM;
    int colBase = (tile % colTiles) * BN;
    int aRow = tid >> 2,  aCol = (tid & 3) << 2;
    int bRow = tid >> 4,  bCol = (tid & 15) << 2;
    float acc[4][4] = {};
    for (int k0 = 0; k0 < 128; k0 += BK) {
        float4 av = make_float4(0.f, 0.f, 0.f, 0.f);
        int gr = rowBase + aRow;
        if (gr < M) av = *(const float4*)(A + (size_t)gr * 128 + k0 + aCol);
        As[aCol + 0][aRow] = av.x;
        As[aCol + 1][aRow] = av.y;
        As[aCol + 2][aRow] = av.z;
        As[aCol + 3][aRow] = av.w;
        *(float4*)&Bs[bRow][bCol] =
            *(const float4*)(W + (size_t)(k0 + bRow) * NOUT + colBase + bCol);
        __syncthreads();
#pragma unroll
        for (int k = 0; k < BK; k++) {
            float a[4], b[4];
#pragma unroll
            for (int i = 0; i < 4; i++) a[i] = As[k][(ty << 2) + i];
#pragma unroll
            for (int j = 0; j < 4; j++) b[j] = Bs[k][(tx << 2) + j];
#pragma unroll
            for (int i = 0; i < 4; i++)
#pragma unroll
                for (int j = 0; j < 4; j++)
                    acc[i][j] = fmaf(a[i], b[j], acc[i][j]);
        }
        __syncthreads();
    }
#pragma unroll
    for (int i = 0; i < 4; i++) {
        int gr = rowBase + (ty << 2) + i;
        if (gr < M)
            *(float4*)(C + (size_t)gr * NOUT + colBase + (tx << 2)) =
                make_float4(acc[i][0], acc[i][1], acc[i][2], acc[i][3]);
    }
}

// ---------------- fused: degree + GEMM1 chunk ----------------
__global__ __launch_bounds__(256) void k_deg_gemm(const void* __restrict__ ei, int E,
        const float* __restrict__ x, const float* __restrict__ W1,
        float* __restrict__ H1, int degBlocks, int tileOff) {
    if ((int)blockIdx.x < degBlocks) {
        int e = blockIdx.x * 256 + threadIdx.x;
        if (e < E) atomicAdd(&g_cnt[edge_at(ei, E, 1, e)], 1);
    } else {
        sgemm_tile<128>(x, W1, H1, N_NODES, tileOff + blockIdx.x - degBlocks);
    }
}

// ---------------- fused: scan(+dinv) + GEMM1 chunk ----------------
__global__ __launch_bounds__(256) void k_scan_gemm(
        const float* __restrict__ x, const float* __restrict__ W1,
        float* __restrict__ H1, int tileOff) {
    if (blockIdx.x == 0) {
        const int T = 256;
        int t = threadIdx.x;
        const int per = (N_NODES + T - 1) / T;
        int s = t * per;
        int e = min(s + per, N_NODES);
        int local = 0;
        for (int i = s; i < e; i++) local += g_cnt[i];
        __shared__ int sm[T];
        sm[t] = local;
        __syncthreads();
        for (int off = 1; off < T; off <<= 1) {
            int v = (t >= off) ? sm[t - off] : 0;
            __syncthreads();
            sm[t] += v;
            __syncthreads();
        }
        int run = sm[t] - local;
        for (int i = s; i < e; i++) {
            int c = g_cnt[i];
            g_rowptr[i] = run;
            run += c;
            g_dinv[i] = rsqrtf((float)c);
        }
        if (t == T - 1) g_rowptr[N_NODES] = sm[T - 1];
    } else {
        sgemm_tile<128>(x, W1, H1, N_NODES, tileOff + blockIdx.x - 1);
    }
}

// ---------------- fused: CSR scatter + GEMM1 chunk ----------------
__global__ __launch_bounds__(256) void k_scat_gemm(const void* __restrict__ ei, int E,
        const float* __restrict__ x, const float* __restrict__ W1,
        float* __restrict__ H1, int scatBlocks, int tileOff) {
    if ((int)blockIdx.x < scatBlocks) {
        int i = blockIdx.x * 256 + threadIdx.x;
        int tot = E + N_NODES;
        if (i >= tot) return;
        int s, d;
        if (i < E) { s = edge_at(ei, E, 0, i); d = edge_at(ei, E, 1, i); }
        else       { s = d = i - E; }
        int pos = g_rowptr[d] + atomicAdd(&g_cursor[d], 1);
        int2 v;
        v.x = s;
        v.y = __float_as_int(g_dinv[s] * g_dinv[d]);
        g_colnrm[pos] = v;
    } else {
        sgemm_tile<128>(x, W1, H1, N_NODES, tileOff + blockIdx.x - scatBlocks);
    }
}

// ---------------- plain GEMM2 ----------------
__global__ __launch_bounds__(256) void k_gemm2(const float* __restrict__ A,
        const float* __restrict__ W, float* __restrict__ C, int M) {
    sgemm_tile<64>(A, W, C, M, blockIdx.x);
}

// ---------------- layer-1 aggregation + bias + relu ----------------
__global__ __launch_bounds__(256) void k_agg1(const float* __restrict__ b1) {
    int warp = (blockIdx.x * blockDim.x + threadIdx.x) >> 5;
    if (warp >= N_NODES) return;
    int lane = threadIdx.x & 31;
    int beg = g_rowptr[warp], end = g_rowptr[warp + 1];
    const int off = lane << 2;
    float4 acc = make_float4(0.f, 0.f, 0.f, 0.f);
    int j = beg;
    for (; j + 4 <= end; j += 4) {
        int2 e0 = g_colnrm[j], e1 = g_colnrm[j + 1];
        int2 e2 = g_colnrm[j + 2], e3 = g_colnrm[j + 3];
        float4 h0 = *(const float4*)(g_H1 + (size_t)e0.x * F1 + off);
        float4 h1 = *(const float4*)(g_H1 + (size_t)e1.x * F1 + off);
        float4 h2 = *(const float4*)(g_H1 + (size_t)e2.x * F1 + off);
        float4 h3 = *(const float4*)(g_H1 + (size_t)e3.x * F1 + off);
        float w0 = __int_as_float(e0.y), w1 = __int_as_float(e1.y);
        float w2 = __int_as_float(e2.y), w3 = __int_as_float(e3.y);
        acc.x = fmaf(h0.x, w0, fmaf(h1.x, w1, fmaf(h2.x, w2, fmaf(h3.x, w3, acc.x))));
        acc.y = fmaf(h0.y, w0, fmaf(h1.y, w1, fmaf(h2.y, w2, fmaf(h3.y, w3, acc.y))));
        acc.z = fmaf(h0.z, w0, fmaf(h1.z, w1, fmaf(h2.z, w2, fmaf(h3.z, w3, acc.z))));
        acc.w = fmaf(h0.w, w0, fmaf(h1.w, w1, fmaf(h2.w, w2, fmaf(h3.w, w3, acc.w))));
    }
    for (; j < end; j++) {
        int2 e0 = g_colnrm[j];
        float w0 = __int_as_float(e0.y);
        float4 h0 = *(const float4*)(g_H1 + (size_t)e0.x * F1 + off);
        acc.x = fmaf(h0.x, w0, acc.x);
        acc.y = fmaf(h0.y, w0, acc.y);
        acc.z = fmaf(h0.z, w0, acc.z);
        acc.w = fmaf(h0.w, w0, acc.w);
    }
    float4 bb = *(const float4*)(b1 + off);
    float4 o;
    o.x = fmaxf(acc.x + bb.x, 0.f);
    o.y = fmaxf(acc.y + bb.y, 0.f);
    o.z = fmaxf(acc.z + bb.z, 0.f);
    o.w = fmaxf(acc.w + bb.w, 0.f);
    *(float4*)(g_A1 + (size_t)warp * F1 + off) = o;
}

// ---------------- layer-2 aggregation + bias + softmax ----------------
__global__ __launch_bounds__(256) void k_agg2(const float* __restrict__ b2,
                                              float* __restrict__ out) {
    int warp = (blockIdx.x * blockDim.x + threadIdx.x) >> 5;
    if (warp >= N_NODES) return;
    int lane = threadIdx.x & 31;
    int beg = g_rowptr[warp], end = g_rowptr[warp + 1];
    const int off = lane << 1;
    float2 acc = make_float2(0.f, 0.f);
    int j = beg;
    for (; j + 4 <= end; j += 4) {
        int2 e0 = g_colnrm[j], e1 = g_colnrm[j + 1];
        int2 e2 = g_colnrm[j + 2], e3 = g_colnrm[j + 3];
        float2 h0 = *(const float2*)(g_H2 + (size_t)e0.x * F2 + off);
        float2 h1 = *(const float2*)(g_H2 + (size_t)e1.x * F2 + off);
        float2 h2 = *(const float2*)(g_H2 + (size_t)e2.x * F2 + off);
        float2 h3 = *(const float2*)(g_H2 + (size_t)e3.x * F2 + off);
        float w0 = __int_as_float(e0.y), w1 = __int_as_float(e1.y);
        float w2 = __int_as_float(e2.y), w3 = __int_as_float(e3.y);
        acc.x = fmaf(h0.x, w0, fmaf(h1.x, w1, fmaf(h2.x, w2, fmaf(h3.x, w3, acc.x))));
        acc.y = fmaf(h0.y, w0, fmaf(h1.y, w1, fmaf(h2.y, w2, fmaf(h3.y, w3, acc.y))));
    }
    for (; j < end; j++) {
        int2 e0 = g_colnrm[j];
        float w0 = __int_as_float(e0.y);
        float2 h0 = *(const float2*)(g_H2 + (size_t)e0.x * F2 + off);
        acc.x = fmaf(h0.x, w0, acc.x);
        acc.y = fmaf(h0.y, w0, acc.y);
    }
    float2 bb = *(const float2*)(b2 + off);
    float l0 = acc.x + bb.x;
    float l1 = acc.y + bb.y;
    float m = fmaxf(l0, l1);
#pragma unroll
    for (int o = 16; o > 0; o >>= 1)
        m = fmaxf(m, __shfl_xor_sync(0xffffffffu, m, o));
    float e0 = __expf(l0 - m);
    float e1 = __expf(l1 - m);
    float s = e0 + e1;
#pragma unroll
    for (int o = 16; o > 0; o >>= 1)
        s += __shfl_xor_sync(0xffffffffu, s, o);
    float inv = 1.0f / s;
    *(float2*)(out + (size_t)warp * F2 + off) = make_float2(e0 * inv, e1 * inv);
}

// ---------------- launch ----------------
extern "C" void kernel_launch(void* const* d_in, const int* in_sizes, int n_in,
                              void* d_out, int out_size) {
    const float* x  = (const float*)d_in[0];
    const void*  ei = d_in[1];
    const float* W1 = (const float*)d_in[2];
    const float* b1 = (const float*)d_in[3];
    const float* W2 = (const float*)d_in[4];
    const float* b2 = (const float*)d_in[5];
    float* out = (float*)d_out;
    int E = in_sizes[1] / 2;

    float *H1, *A1, *H2;
    cudaGetSymbolAddress((void**)&H1, g_H1);
    cudaGetSymbolAddress((void**)&A1, g_A1);
    cudaGetSymbolAddress((void**)&H2, g_H2);

    const int mTiles = (N_NODES + 63) / 64;    // 782
    const int g1Tiles = 2 * mTiles;            // 1564 (NOUT=128 -> 2 col tiles)
    const int g2Tiles = 1 * mTiles;            // 782

    // GEMM1 tile chunks distributed across the three CSR-phase kernels
    const int c1 = 520;
    const int c2 = 480;
    const int c3 = g1Tiles - c1 - c2;          // 564

    const int degBlocks  = (E + 255) / 256;
    const int scatBlocks = (E + N_NODES + 255) / 256;

    k_init_detect<<<(N_NODES + 255) / 256, 256>>>(ei);
    k_deg_gemm<<<degBlocks + c1, 256>>>(ei, E, x, W1, H1, degBlocks, 0);
    k_scan_gemm<<<1 + c2, 256>>>(x, W1, H1, c1);
    k_scat_gemm<<<scatBlocks + c3, 256>>>(ei, E, x, W1, H1, scatBlocks, c1 + c2);

    k_agg1<<<(N_NODES * 32 + 255) / 256, 256>>>(b1);
    k_gemm2<<<g2Tiles, 256>>>(A1, W2, H2, N_NODES);
    k_agg2<<<(N_NODES * 32 + 255) / 256, 256>>>(b2, out);
}

// round 8
// speedup vs baseline: 1.4588x; 1.0366x over previous
#include <cuda_runtime.h>
#include <cuda_bf16.h>
#include <cstdint>

#define N_NODES 50000
#define MAX_E   800000
#define MAX_TOT (MAX_E + N_NODES)
#define F1 128
#define F2 64

// ---------------- scratch (no allocations allowed) ----------------
__device__ int   g_cnt[N_NODES];
__device__ int   g_cursor[N_NODES];
__device__ int   g_rowptr[N_NODES + 1];
__device__ int2  g_colnrm[MAX_TOT];      // .x = src col, .y = bitcast(norm)
__device__ float g_dinv[N_NODES];
__device__ float g_H1[(size_t)N_NODES * F1];   // x @ W1
__device__ float g_A1[(size_t)N_NODES * F1];   // relu(agg + b1)
__device__ float g_H2[(size_t)N_NODES * F2];   // A1 @ W2
__device__ int   g_is64;

// ---------------- edge dtype probe + init ----------------
__global__ void k_init_detect(const void* ei) {
    int i = blockIdx.x * blockDim.x + threadIdx.x;
    if (i < N_NODES) { g_cnt[i] = 1; g_cursor[i] = 0; }
    if (i == 0) {
        const long long* p = (const long long*)ei;
        int ok = 1;
        for (int j = 0; j < 64; j++) {
            long long v = p[j];
            if (v < 0 || v >= N_NODES) { ok = 0; break; }
        }
        g_is64 = ok;
    }
}

__device__ __forceinline__ int edge_at(const void* ei, int E, int which, int idx) {
    if (g_is64) return (int)((const long long*)ei)[(size_t)which * E + idx];
    return ((const int*)ei)[(size_t)which * E + idx];
}

__global__ void k_degree(const void* __restrict__ ei, int E) {
    int e = blockIdx.x * blockDim.x + threadIdx.x;
    if (e < E) atomicAdd(&g_cnt[edge_at(ei, E, 1, e)], 1);
}

// ---------------- exclusive scan + dinv (single block) ----------------
__global__ void k_scan() {
    const int T = 1024;
    int t = threadIdx.x;
    const int per = (N_NODES + T - 1) / T;
    int s = t * per;
    int e = min(s + per, N_NODES);
    int local = 0;
    for (int i = s; i < e; i++) local += g_cnt[i];
    __shared__ int sm[T];
    sm[t] = local;
    __syncthreads();
    for (int off = 1; off < T; off <<= 1) {
        int v = (t >= off) ? sm[t - off] : 0;
        __syncthreads();
        sm[t] += v;
        __syncthreads();
    }
    int run = sm[t] - local;
    for (int i = s; i < e; i++) {
        int c = g_cnt[i];
        g_rowptr[i] = run;
        run += c;
        g_dinv[i] = rsqrtf((float)c);
    }
    if (t == T - 1) g_rowptr[N_NODES] = sm[T - 1];
}

// ---------------- CSR scatter (edges + self loops), packed 8B stores ----------------
__global__ void k_scatter(const void* __restrict__ ei, int E) {
    int i = blockIdx.x * blockDim.x + threadIdx.x;
    int tot = E + N_NODES;
    if (i >= tot) return;
    int s, d;
    if (i < E) { s = edge_at(ei, E, 0, i); d = edge_at(ei, E, 1, i); }
    else       { s = d = i - E; }
    int pos = g_rowptr[d] + atomicAdd(&g_cursor[d], 1);
    int2 v;
    v.x = s;
    v.y = __float_as_int(g_dinv[s] * g_dinv[d]);
    g_colnrm[pos] = v;
}

// ---------------- fp32 SGEMM (round-1, verbatim): C[M,N] = A[M,K] @ B[K,N] ----------------
__global__ __launch_bounds__(256) void k_sgemm(int M, int N, int K,
        const float* __restrict__ A, const float* __restrict__ B,
        float* __restrict__ C) {
    const int BM = 64, BN = 64, BK = 16;
    __shared__ float As[BK][BM];
    __shared__ float Bs[BK][BN];
    int tid = threadIdx.x;
    int tx = tid & 15, ty = tid >> 4;
    int rowBase = blockIdx.y * BM, colBase = blockIdx.x * BN;
    int aRow = tid >> 2,  aCol = (tid & 3) << 2;
    int bRow = tid >> 4,  bCol = (tid & 15) << 2;
    float acc[4][4] = {};
    for (int k0 = 0; k0 < K; k0 += BK) {
        float4 av = make_float4(0.f, 0.f, 0.f, 0.f);
        int gr = rowBase + aRow;
        if (gr < M) av = *(const float4*)(A + (size_t)gr * K + k0 + aCol);
        As[aCol + 0][aRow] = av.x;
        As[aCol + 1][aRow] = av.y;
        As[aCol + 2][aRow] = av.z;
        As[aCol + 3][aRow] = av.w;
        *(float4*)&Bs[bRow][bCol] =
            *(const float4*)(B + (size_t)(k0 + bRow) * N + colBase + bCol);
        __syncthreads();
#pragma unroll
        for (int k = 0; k < BK; k++) {
            float a[4], b[4];
#pragma unroll
            for (int i = 0; i < 4; i++) a[i] = As[k][(ty << 2) + i];
#pragma unroll
            for (int j = 0; j < 4; j++) b[j] = Bs[k][(tx << 2) + j];
#pragma unroll
            for (int i = 0; i < 4; i++)
#pragma unroll
                for (int j = 0; j < 4; j++)
                    acc[i][j] = fmaf(a[i], b[j], acc[i][j]);
        }
        __syncthreads();
    }
#pragma unroll
    for (int i = 0; i < 4; i++) {
        int gr = rowBase + (ty << 2) + i;
        if (gr < M)
            *(float4*)(C + (size_t)gr * N + colBase + (tx << 2)) =
                make_float4(acc[i][0], acc[i][1], acc[i][2], acc[i][3]);
    }
}

// ---------------- layer-1 aggregation + bias + relu ----------------
__global__ __launch_bounds__(256) void k_agg1(const float* __restrict__ b1) {
    int warp = (blockIdx.x * blockDim.x + threadIdx.x) >> 5;
    if (warp >= N_NODES) return;
    int lane = threadIdx.x & 31;
    int beg = g_rowptr[warp], end = g_rowptr[warp + 1];
    const int off = lane << 2;
    float4 acc = make_float4(0.f, 0.f, 0.f, 0.f);
    int j = beg;
    for (; j + 4 <= end; j += 4) {
        int2 e0 = g_colnrm[j], e1 = g_colnrm[j + 1];
        int2 e2 = g_colnrm[j + 2], e3 = g_colnrm[j + 3];
        float4 h0 = *(const float4*)(g_H1 + (size_t)e0.x * F1 + off);
        float4 h1 = *(const float4*)(g_H1 + (size_t)e1.x * F1 + off);
        float4 h2 = *(const float4*)(g_H1 + (size_t)e2.x * F1 + off);
        float4 h3 = *(const float4*)(g_H1 + (size_t)e3.x * F1 + off);
        float w0 = __int_as_float(e0.y), w1 = __int_as_float(e1.y);
        float w2 = __int_as_float(e2.y), w3 = __int_as_float(e3.y);
        acc.x = fmaf(h0.x, w0, fmaf(h1.x, w1, fmaf(h2.x, w2, fmaf(h3.x, w3, acc.x))));
        acc.y = fmaf(h0.y, w0, fmaf(h1.y, w1, fmaf(h2.y, w2, fmaf(h3.y, w3, acc.y))));
        acc.z = fmaf(h0.z, w0, fmaf(h1.z, w1, fmaf(h2.z, w2, fmaf(h3.z, w3, acc.z))));
        acc.w = fmaf(h0.w, w0, fmaf(h1.w, w1, fmaf(h2.w, w2, fmaf(h3.w, w3, acc.w))));
    }
    for (; j < end; j++) {
        int2 e0 = g_colnrm[j];
        float w0 = __int_as_float(e0.y);
        float4 h0 = *(const float4*)(g_H1 + (size_t)e0.x * F1 + off);
        acc.x = fmaf(h0.x, w0, acc.x);
        acc.y = fmaf(h0.y, w0, acc.y);
        acc.z = fmaf(h0.z, w0, acc.z);
        acc.w = fmaf(h0.w, w0, acc.w);
    }
    float4 bb = *(const float4*)(b1 + off);
    float4 o;
    o.x = fmaxf(acc.x + bb.x, 0.f);
    o.y = fmaxf(acc.y + bb.y, 0.f);
    o.z = fmaxf(acc.z + bb.z, 0.f);
    o.w = fmaxf(acc.w + bb.w, 0.f);
    *(float4*)(g_A1 + (size_t)warp * F1 + off) = o;
}

// ---------------- layer-2 aggregation + bias + softmax ----------------
__global__ __launch_bounds__(256) void k_agg2(const float* __restrict__ b2,
                                              float* __restrict__ out) {
    int warp = (blockIdx.x * blockDim.x + threadIdx.x) >> 5;
    if (warp >= N_NODES) return;
    int lane = threadIdx.x & 31;
    int beg = g_rowptr[warp], end = g_rowptr[warp + 1];
    const int off = lane << 1;
    float2 acc = make_float2(0.f, 0.f);
    int j = beg;
    for (; j + 4 <= end; j += 4) {
        int2 e0 = g_colnrm[j], e1 = g_colnrm[j + 1];
        int2 e2 = g_colnrm[j + 2], e3 = g_colnrm[j + 3];
        float2 h0 = *(const float2*)(g_H2 + (size_t)e0.x * F2 + off);
        float2 h1 = *(const float2*)(g_H2 + (size_t)e1.x * F2 + off);
        float2 h2 = *(const float2*)(g_H2 + (size_t)e2.x * F2 + off);
        float2 h3 = *(const float2*)(g_H2 + (size_t)e3.x * F2 + off);
        float w0 = __int_as_float(e0.y), w1 = __int_as_float(e1.y);
        float w2 = __int_as_float(e2.y), w3 = __int_as_float(e3.y);
        acc.x = fmaf(h0.x, w0, fmaf(h1.x, w1, fmaf(h2.x, w2, fmaf(h3.x, w3, acc.x))));
        acc.y = fmaf(h0.y, w0, fmaf(h1.y, w1, fmaf(h2.y, w2, fmaf(h3.y, w3, acc.y))));
    }
    for (; j < end; j++) {
        int2 e0 = g_colnrm[j];
        float w0 = __int_as_float(e0.y);
        float2 h0 = *(const float2*)(g_H2 + (size_t)e0.x * F2 + off);
        acc.x = fmaf(h0.x, w0, acc.x);
        acc.y = fmaf(h0.y, w0, acc.y);
    }
    float2 bb = *(const float2*)(b2 + off);
    float l0 = acc.x + bb.x;
    float l1 = acc.y + bb.y;
    float m = fmaxf(l0, l1);
#pragma unroll
    for (int o = 16; o > 0; o >>= 1)
        m = fmaxf(m, __shfl_xor_sync(0xffffffffu, m, o));
    float e0 = __expf(l0 - m);
    float e1 = __expf(l1 - m);
    float s = e0 + e1;
#pragma unroll
    for (int o = 16; o > 0; o >>= 1)
        s += __shfl_xor_sync(0xffffffffu, s, o);
    float inv = 1.0f / s;
    *(float2*)(out + (size_t)warp * F2 + off) = make_float2(e0 * inv, e1 * inv);
}

// ---------------- launch ----------------
extern "C" void kernel_launch(void* const* d_in, const int* in_sizes, int n_in,
                              void* d_out, int out_size) {
    const float* x  = (const float*)d_in[0];
    const void*  ei = d_in[1];
    const float* W1 = (const float*)d_in[2];
    const float* b1 = (const float*)d_in[3];
    const float* W2 = (const float*)d_in[4];
    const float* b2 = (const float*)d_in[5];
    float* out = (float*)d_out;
    int E = in_sizes[1] / 2;

    float *H1, *A1, *H2;
    cudaGetSymbolAddress((void**)&H1, g_H1);
    cudaGetSymbolAddress((void**)&A1, g_A1);
    cudaGetSymbolAddress((void**)&H2, g_H2);

    const int mTiles = (N_NODES + 63) / 64;   // 782

    k_init_detect<<<(N_NODES + 255) / 256, 256>>>(ei);
    k_degree<<<(E + 255) / 256, 256>>>(ei, E);
    k_scan<<<1, 1024>>>();
    k_scatter<<<(E + N_NODES + 255) / 256, 256>>>(ei, E);

    k_sgemm<<<dim3(2, mTiles), 256>>>(N_NODES, F1, F1, x, W1, H1);
    k_agg1<<<(N_NODES * 32 + 255) / 256, 256>>>(b1);
    k_sgemm<<<dim3(1, mTiles), 256>>>(N_NODES, F2, F1, A1, W2, H2);
    k_agg2<<<(N_NODES * 32 + 255) / 256, 256>>>(b2, out);
}

// round 9
// speedup vs baseline: 1.5203x; 1.0422x over previous
#include <cuda_runtime.h>
#include <cuda_fp16.h>
#include <cstdint>

#define N_NODES 50000
#define MAX_E   800000
#define MAX_TOT (MAX_E + N_NODES)
#define F1 128
#define F2 64

// ---------------- scratch (no allocations allowed) ----------------
__device__ int    g_cnt[N_NODES];
__device__ int    g_cursor[N_NODES];
__device__ int    g_rowptr[N_NODES + 1];
__device__ int2   g_colnrm[MAX_TOT];     // .x = src col, .y = bitcast(norm)
__device__ float  g_dinv[N_NODES];
__device__ __half g_H1h[(size_t)N_NODES * F1];  // x @ W1   (fp16 storage)
__device__ float  g_A1[(size_t)N_NODES * F1];   // relu(agg + b1)  (fp32)
__device__ __half g_H2h[(size_t)N_NODES * F2];  // A1 @ W2  (fp16 storage)
__device__ int    g_is64;

// ---------------- edge dtype probe + init ----------------
__global__ void k_init_detect(const void* ei) {
    int i = blockIdx.x * blockDim.x + threadIdx.x;
    if (i < N_NODES) { g_cnt[i] = 1; g_cursor[i] = 0; }
    if (i == 0) {
        const long long* p = (const long long*)ei;
        int ok = 1;
        for (int j = 0; j < 64; j++) {
            long long v = p[j];
            if (v < 0 || v >= N_NODES) { ok = 0; break; }
        }
        g_is64 = ok;
    }
}

__device__ __forceinline__ int edge_at(const void* ei, int E, int which, int idx) {
    if (g_is64) return (int)((const long long*)ei)[(size_t)which * E + idx];
    return ((const int*)ei)[(size_t)which * E + idx];
}

__global__ void k_degree(const void* __restrict__ ei, int E) {
    int e = blockIdx.x * blockDim.x + threadIdx.x;
    if (e < E) atomicAdd(&g_cnt[edge_at(ei, E, 1, e)], 1);
}

// ---------------- exclusive scan + dinv (single block) ----------------
__global__ void k_scan() {
    const int T = 1024;
    int t = threadIdx.x;
    const int per = (N_NODES + T - 1) / T;
    int s = t * per;
    int e = min(s + per, N_NODES);
    int local = 0;
    for (int i = s; i < e; i++) local += g_cnt[i];
    __shared__ int sm[T];
    sm[t] = local;
    __syncthreads();
    for (int off = 1; off < T; off <<= 1) {
        int v = (t >= off) ? sm[t - off] : 0;
        __syncthreads();
        sm[t] += v;
        __syncthreads();
    }
    int run = sm[t] - local;
    for (int i = s; i < e; i++) {
        int c = g_cnt[i];
        g_rowptr[i] = run;
        run += c;
        g_dinv[i] = rsqrtf((float)c);
    }
    if (t == T - 1) g_rowptr[N_NODES] = sm[T - 1];
}

// ---------------- CSR scatter (edges + self loops), packed 8B stores ----------------
__global__ void k_scatter(const void* __restrict__ ei, int E) {
    int i = blockIdx.x * blockDim.x + threadIdx.x;
    int tot = E + N_NODES;
    if (i >= tot) return;
    int s, d;
    if (i < E) { s = edge_at(ei, E, 0, i); d = edge_at(ei, E, 1, i); }
    else       { s = d = i - E; }
    int pos = g_rowptr[d] + atomicAdd(&g_cursor[d], 1);
    int2 v;
    v.x = s;
    v.y = __float_as_int(g_dinv[s] * g_dinv[d]);
    g_colnrm[pos] = v;
}

// ---------------- fp32 SGEMM (round-1 body), templated output type ----------------
// C[M,N] = A[M,K] @ B[K,N]; OUT_HALF stores half, else float.
template<int OUT_HALF>
__global__ __launch_bounds__(256) void k_sgemm(int M, int N, int K,
        const float* __restrict__ A, const float* __restrict__ B,
        void* __restrict__ Cv) {
    const int BM = 64, BN = 64, BK = 16;
    __shared__ float As[BK][BM];
    __shared__ float Bs[BK][BN];
    int tid = threadIdx.x;
    int tx = tid & 15, ty = tid >> 4;
    int rowBase = blockIdx.y * BM, colBase = blockIdx.x * BN;
    int aRow = tid >> 2,  aCol = (tid & 3) << 2;
    int bRow = tid >> 4,  bCol = (tid & 15) << 2;
    float acc[4][4] = {};
    for (int k0 = 0; k0 < K; k0 += BK) {
        float4 av = make_float4(0.f, 0.f, 0.f, 0.f);
        int gr = rowBase + aRow;
        if (gr < M) av = *(const float4*)(A + (size_t)gr * K + k0 + aCol);
        As[aCol + 0][aRow] = av.x;
        As[aCol + 1][aRow] = av.y;
        As[aCol + 2][aRow] = av.z;
        As[aCol + 3][aRow] = av.w;
        *(float4*)&Bs[bRow][bCol] =
            *(const float4*)(B + (size_t)(k0 + bRow) * N + colBase + bCol);
        __syncthreads();
#pragma unroll
        for (int k = 0; k < BK; k++) {
            float a[4], b[4];
#pragma unroll
            for (int i = 0; i < 4; i++) a[i] = As[k][(ty << 2) + i];
#pragma unroll
            for (int j = 0; j < 4; j++) b[j] = Bs[k][(tx << 2) + j];
#pragma unroll
            for (int i = 0; i < 4; i++)
#pragma unroll
                for (int j = 0; j < 4; j++)
                    acc[i][j] = fmaf(a[i], b[j], acc[i][j]);
        }
        __syncthreads();
    }
#pragma unroll
    for (int i = 0; i < 4; i++) {
        int gr = rowBase + (ty << 2) + i;
        if (gr < M) {
            if (OUT_HALF) {
                __half* C = (__half*)Cv;
                __half2 p0 = __floats2half2_rn(acc[i][0], acc[i][1]);
                __half2 p1 = __floats2half2_rn(acc[i][2], acc[i][3]);
                uint2 pk;
                pk.x = *reinterpret_cast<uint32_t*>(&p0);
                pk.y = *reinterpret_cast<uint32_t*>(&p1);
                *(uint2*)(C + (size_t)gr * N + colBase + (tx << 2)) = pk;
            } else {
                float* C = (float*)Cv;
                *(float4*)(C + (size_t)gr * N + colBase + (tx << 2)) =
                    make_float4(acc[i][0], acc[i][1], acc[i][2], acc[i][3]);
            }
        }
    }
}

// ---------------- layer-1 aggregation (fp16 gather, fp32 accum) + bias + relu ----------------
__device__ __forceinline__ float4 ldh4(const __half* p) {
    uint2 raw = *(const uint2*)p;
    __half2 h0 = *reinterpret_cast<__half2*>(&raw.x);
    __half2 h1 = *reinterpret_cast<__half2*>(&raw.y);
    float2 f0 = __half22float2(h0);
    float2 f1 = __half22float2(h1);
    return make_float4(f0.x, f0.y, f1.x, f1.y);
}

__global__ __launch_bounds__(256) void k_agg1(const float* __restrict__ b1) {
    int warp = (blockIdx.x * blockDim.x + threadIdx.x) >> 5;
    if (warp >= N_NODES) return;
    int lane = threadIdx.x & 31;
    int beg = g_rowptr[warp], end = g_rowptr[warp + 1];
    const int off = lane << 2;
    float4 acc = make_float4(0.f, 0.f, 0.f, 0.f);
    int j = beg;
    for (; j + 4 <= end; j += 4) {
        int2 e0 = g_colnrm[j], e1 = g_colnrm[j + 1];
        int2 e2 = g_colnrm[j + 2], e3 = g_colnrm[j + 3];
        float4 h0 = ldh4(g_H1h + (size_t)e0.x * F1 + off);
        float4 h1 = ldh4(g_H1h + (size_t)e1.x * F1 + off);
        float4 h2 = ldh4(g_H1h + (size_t)e2.x * F1 + off);
        float4 h3 = ldh4(g_H1h + (size_t)e3.x * F1 + off);
        float w0 = __int_as_float(e0.y), w1 = __int_as_float(e1.y);
        float w2 = __int_as_float(e2.y), w3 = __int_as_float(e3.y);
        acc.x = fmaf(h0.x, w0, fmaf(h1.x, w1, fmaf(h2.x, w2, fmaf(h3.x, w3, acc.x))));
        acc.y = fmaf(h0.y, w0, fmaf(h1.y, w1, fmaf(h2.y, w2, fmaf(h3.y, w3, acc.y))));
        acc.z = fmaf(h0.z, w0, fmaf(h1.z, w1, fmaf(h2.z, w2, fmaf(h3.z, w3, acc.z))));
        acc.w = fmaf(h0.w, w0, fmaf(h1.w, w1, fmaf(h2.w, w2, fmaf(h3.w, w3, acc.w))));
    }
    for (; j < end; j++) {
        int2 e0 = g_colnrm[j];
        float w0 = __int_as_float(e0.y);
        float4 h0 = ldh4(g_H1h + (size_t)e0.x * F1 + off);
        acc.x = fmaf(h0.x, w0, acc.x);
        acc.y = fmaf(h0.y, w0, acc.y);
        acc.z = fmaf(h0.z, w0, acc.z);
        acc.w = fmaf(h0.w, w0, acc.w);
    }
    float4 bb = *(const float4*)(b1 + off);
    float4 o;
    o.x = fmaxf(acc.x + bb.x, 0.f);
    o.y = fmaxf(acc.y + bb.y, 0.f);
    o.z = fmaxf(acc.z + bb.z, 0.f);
    o.w = fmaxf(acc.w + bb.w, 0.f);
    *(float4*)(g_A1 + (size_t)warp * F1 + off) = o;
}

// ---------------- layer-2 aggregation (fp16 gather) + bias + softmax ----------------
__global__ __launch_bounds__(256) void k_agg2(const float* __restrict__ b2,
                                              float* __restrict__ out) {
    int warp = (blockIdx.x * blockDim.x + threadIdx.x) >> 5;
    if (warp >= N_NODES) return;
    int lane = threadIdx.x & 31;
    int beg = g_rowptr[warp], end = g_rowptr[warp + 1];
    const int off = lane << 1;
    float2 acc = make_float2(0.f, 0.f);
    int j = beg;
    for (; j + 4 <= end; j += 4) {
        int2 e0 = g_colnrm[j], e1 = g_colnrm[j + 1];
        int2 e2 = g_colnrm[j + 2], e3 = g_colnrm[j + 3];
        __half2 p0 = *(const __half2*)(g_H2h + (size_t)e0.x * F2 + off);
        __half2 p1 = *(const __half2*)(g_H2h + (size_t)e1.x * F2 + off);
        __half2 p2 = *(const __half2*)(g_H2h + (size_t)e2.x * F2 + off);
        __half2 p3 = *(const __half2*)(g_H2h + (size_t)e3.x * F2 + off);
        float2 h0 = __half22float2(p0), h1 = __half22float2(p1);
        float2 h2 = __half22float2(p2), h3 = __half22float2(p3);
        float w0 = __int_as_float(e0.y), w1 = __int_as_float(e1.y);
        float w2 = __int_as_float(e2.y), w3 = __int_as_float(e3.y);
        acc.x = fmaf(h0.x, w0, fmaf(h1.x, w1, fmaf(h2.x, w2, fmaf(h3.x, w3, acc.x))));
        acc.y = fmaf(h0.y, w0, fmaf(h1.y, w1, fmaf(h2.y, w2, fmaf(h3.y, w3, acc.y))));
    }
    for (; j < end; j++) {
        int2 e0 = g_colnrm[j];
        float w0 = __int_as_float(e0.y);
        float2 h0 = __half22float2(*(const __half2*)(g_H2h + (size_t)e0.x * F2 + off));
        acc.x = fmaf(h0.x, w0, acc.x);
        acc.y = fmaf(h0.y, w0, acc.y);
    }
    float2 bb = *(const float2*)(b2 + off);
    float l0 = acc.x + bb.x;
    float l1 = acc.y + bb.y;
    float m = fmaxf(l0, l1);
#pragma unroll
    for (int o = 16; o > 0; o >>= 1)
        m = fmaxf(m, __shfl_xor_sync(0xffffffffu, m, o));
    float e0 = __expf(l0 - m);
    float e1 = __expf(l1 - m);
    float s = e0 + e1;
#pragma unroll
    for (int o = 16; o > 0; o >>= 1)
        s += __shfl_xor_sync(0xffffffffu, s, o);
    float inv = 1.0f / s;
    *(float2*)(out + (size_t)warp * F2 + off) = make_float2(e0 * inv, e1 * inv);
}

// ---------------- launch ----------------
extern "C" void kernel_launch(void* const* d_in, const int* in_sizes, int n_in,
                              void* d_out, int out_size) {
    const float* x  = (const float*)d_in[0];
    const void*  ei = d_in[1];
    const float* W1 = (const float*)d_in[2];
    const float* b1 = (const float*)d_in[3];
    const float* W2 = (const float*)d_in[4];
    const float* b2 = (const float*)d_in[5];
    float* out = (float*)d_out;
    int E = in_sizes[1] / 2;

    __half *H1h, *H2h;
    float  *A1;
    cudaGetSymbolAddress((void**)&H1h, g_H1h);
    cudaGetSymbolAddress((void**)&A1,  g_A1);
    cudaGetSymbolAddress((void**)&H2h, g_H2h);

    const int mTiles = (N_NODES + 63) / 64;   // 782

    k_init_detect<<<(N_NODES + 255) / 256, 256>>>(ei);
    k_degree<<<(E + 255) / 256, 256>>>(ei, E);
    k_scan<<<1, 1024>>>();
    k_scatter<<<(E + N_NODES + 255) / 256, 256>>>(ei, E);

    k_sgemm<1><<<dim3(2, mTiles), 256>>>(N_NODES, F1, F1, x, W1, H1h);
    k_agg1<<<(N_NODES * 32 + 255) / 256, 256>>>(b1);
    k_sgemm<1><<<dim3(1, mTiles), 256>>>(N_NODES, F2, F1, A1, W2, H2h);
    k_agg2<<<(N_NODES * 32 + 255) / 256, 256>>>(b2, out);
}

// round 10
// speedup vs baseline: 1.8159x; 1.1944x over previous
#include <cuda_runtime.h>
#include <cuda_fp16.h>
#include <cstdint>

#define N_NODES 50000
#define MAX_E   800000
#define MAX_TOT (MAX_E + N_NODES)
#define F1 128
#define F2 64

// ---------------- scratch (no allocations allowed) ----------------
__device__ int    g_cnt[N_NODES];
__device__ int    g_cursor[N_NODES];
__device__ int    g_rowptr[N_NODES + 1];
__device__ int2   g_colnrm[MAX_TOT];     // .x = src col, .y = bitcast(norm)
__device__ float  g_dinv[N_NODES];
__device__ __half g_H1h[(size_t)N_NODES * F1];  // x @ W1      (fp16)
__device__ __half g_A1h[(size_t)N_NODES * F1];  // relu(agg+b) (fp16)
__device__ __half g_H2h[(size_t)N_NODES * F2];  // A1 @ W2     (fp16)
__device__ int    g_is64;

// ---------------- edge dtype probe + init ----------------
__global__ void k_init_detect(const void* ei) {
    int i = blockIdx.x * blockDim.x + threadIdx.x;
    if (i < N_NODES) { g_cnt[i] = 1; g_cursor[i] = 0; }
    if (i == 0) {
        const long long* p = (const long long*)ei;
        int ok = 1;
        for (int j = 0; j < 64; j++) {
            long long v = p[j];
            if (v < 0 || v >= N_NODES) { ok = 0; break; }
        }
        g_is64 = ok;
    }
}

__device__ __forceinline__ int edge_at(const void* ei, int E, int which, int idx) {
    if (g_is64) return (int)((const long long*)ei)[(size_t)which * E + idx];
    return ((const int*)ei)[(size_t)which * E + idx];
}

__global__ void k_degree(const void* __restrict__ ei, int E) {
    int e = blockIdx.x * blockDim.x + threadIdx.x;
    if (e < E) atomicAdd(&g_cnt[edge_at(ei, E, 1, e)], 1);
}

// ---------------- exclusive scan + dinv (single block) ----------------
__global__ void k_scan() {
    const int T = 1024;
    int t = threadIdx.x;
    const int per = (N_NODES + T - 1) / T;
    int s = t * per;
    int e = min(s + per, N_NODES);
    int local = 0;
    for (int i = s; i < e; i++) local += g_cnt[i];
    __shared__ int sm[T];
    sm[t] = local;
    __syncthreads();
    for (int off = 1; off < T; off <<= 1) {
        int v = (t >= off) ? sm[t - off] : 0;
        __syncthreads();
        sm[t] += v;
        __syncthreads();
    }
    int run = sm[t] - local;
    for (int i = s; i < e; i++) {
        int c = g_cnt[i];
        g_rowptr[i] = run;
        run += c;
        g_dinv[i] = rsqrtf((float)c);
    }
    if (t == T - 1) g_rowptr[N_NODES] = sm[T - 1];
}

// ---------------- CSR scatter (edges + self loops), packed 8B stores ----------------
__global__ void k_scatter(const void* __restrict__ ei, int E) {
    int i = blockIdx.x * blockDim.x + threadIdx.x;
    int tot = E + N_NODES;
    if (i >= tot) return;
    int s, d;
    if (i < E) { s = edge_at(ei, E, 0, i); d = edge_at(ei, E, 1, i); }
    else       { s = d = i - E; }
    int pos = g_rowptr[d] + atomicAdd(&g_cursor[d], 1);
    int2 v;
    v.x = s;
    v.y = __float_as_int(g_dinv[s] * g_dinv[d]);
    g_colnrm[pos] = v;
}

// ============ fp16 mma.sync GEMM: C[M,NOUT] = A[M,128] @ W[128,NOUT] ============
// Fragment layout identical to the round-3 kernel (verified correct), single
// product, fp16 inputs, fp32 accumulate, fp16 output.
__device__ __forceinline__ void mma_f16(float* c,
        uint32_t a0, uint32_t a1, uint32_t a2, uint32_t a3,
        uint32_t b0, uint32_t b1) {
    asm volatile("mma.sync.aligned.m16n8k16.row.col.f32.f16.f16.f32 "
        "{%0,%1,%2,%3}, {%4,%5,%6,%7}, {%8,%9}, {%0,%1,%2,%3};"
        : "+f"(c[0]), "+f"(c[1]), "+f"(c[2]), "+f"(c[3])
        : "r"(a0), "r"(a1), "r"(a2), "r"(a3), "r"(b0), "r"(b1));
}

template<int NOUT, int AHALF>
__global__ __launch_bounds__(256, 2) void k_gemm_mma(const void* __restrict__ Av,
        const float* __restrict__ W, __half* __restrict__ C, int M) {
    extern __shared__ __align__(16) char smem[];
    const int LDA = 136;
    __half* Ah = (__half*)smem;            // 128 x LDA
    __half* Bh = Ah + 128 * LDA;           // NOUT x LDA (W^T)

    int tid = threadIdx.x, lane = tid & 31, wid = tid >> 5;
    int rowBase = blockIdx.x * 128;

    // ---- load A tile ----
    {
        int r = tid >> 1, c0 = (tid & 1) * 64;
        bool valid = (rowBase + r) < M;
        if (AHALF) {
            const __half* arow = (const __half*)Av + (size_t)(rowBase + r) * 128 + c0;
#pragma unroll
            for (int i = 0; i < 8; i++) {
                uint4 v = valid ? *(const uint4*)(arow + i * 8)
                                : make_uint4(0u, 0u, 0u, 0u);
                *(uint4*)(Ah + r * LDA + c0 + i * 8) = v;
            }
        } else {
            const float* arow = (const float*)Av + (size_t)(rowBase + r) * 128 + c0;
#pragma unroll
            for (int i = 0; i < 8; i++) {
                float4 v0 = valid ? *(const float4*)(arow + i * 8)
                                  : make_float4(0.f, 0.f, 0.f, 0.f);
                float4 v1 = valid ? *(const float4*)(arow + i * 8 + 4)
                                  : make_float4(0.f, 0.f, 0.f, 0.f);
                __half2 h0 = __floats2half2_rn(v0.x, v0.y);
                __half2 h1 = __floats2half2_rn(v0.z, v0.w);
                __half2 h2 = __floats2half2_rn(v1.x, v1.y);
                __half2 h3 = __floats2half2_rn(v1.z, v1.w);
                uint4 pk;
                pk.x = *reinterpret_cast<uint32_t*>(&h0);
                pk.y = *reinterpret_cast<uint32_t*>(&h1);
                pk.z = *reinterpret_cast<uint32_t*>(&h2);
                pk.w = *reinterpret_cast<uint32_t*>(&h3);
                *(uint4*)(Ah + r * LDA + c0 + i * 8) = pk;
            }
        }
    }
    // ---- load + transpose + convert W: Wt[n][k] ----
    for (int idx = tid * 4; idx < 128 * NOUT; idx += 256 * 4) {
        int k = idx / NOUT, n0 = idx % NOUT;
        float4 w = *(const float4*)(W + idx);
        Bh[(n0 + 0) * LDA + k] = __float2half_rn(w.x);
        Bh[(n0 + 1) * LDA + k] = __float2half_rn(w.y);
        Bh[(n0 + 2) * LDA + k] = __float2half_rn(w.z);
        Bh[(n0 + 3) * LDA + k] = __float2half_rn(w.w);
    }
    __syncthreads();

    // ---- warp tiling (round-3 verified) ----
    const int WCOLS = NOUT / 32;          // 4 (128) or 2 (64)
    const int WROWS = 8 / WCOLS;          // 2 or 4
    const int MT    = 128 / (WROWS * 16); // 4 or 2
    int wr = wid / WCOLS, wc = wid % WCOLS;
    int mBase = wr * (MT * 16);
    int nBase = wc * 32;
    int g = lane >> 2, t2 = (lane & 3) * 2;

    float acc[MT][4][4];
#pragma unroll
    for (int mt = 0; mt < MT; mt++)
#pragma unroll
        for (int nt = 0; nt < 4; nt++)
#pragma unroll
            for (int j = 0; j < 4; j++) acc[mt][nt][j] = 0.f;

#pragma unroll
    for (int ks = 0; ks < 8; ks++) {
        int k0 = ks * 16;
        uint32_t af[MT][4];
#pragma unroll
        for (int mt = 0; mt < MT; mt++) {
            int r0 = mBase + mt * 16 + g;
            int o0 = r0 * LDA + k0 + t2;
            int o1 = (r0 + 8) * LDA + k0 + t2;
            af[mt][0] = *(const uint32_t*)(Ah + o0);
            af[mt][1] = *(const uint32_t*)(Ah + o1);
            af[mt][2] = *(const uint32_t*)(Ah + o0 + 8);
            af[mt][3] = *(const uint32_t*)(Ah + o1 + 8);
        }
#pragma unroll
        for (int nt = 0; nt < 4; nt++) {
            int n = nBase + nt * 8 + g;
            int bb = n * LDA + k0 + t2;
            uint32_t b0 = *(const uint32_t*)(Bh + bb);
            uint32_t b1 = *(const uint32_t*)(Bh + bb + 8);
#pragma unroll
            for (int mt = 0; mt < MT; mt++)
                mma_f16(acc[mt][nt], af[mt][0], af[mt][1], af[mt][2], af[mt][3], b0, b1);
        }
    }

    // ---- epilogue: fp32 acc -> fp16 store ----
#pragma unroll
    for (int mt = 0; mt < MT; mt++) {
        int row0 = rowBase + mBase + mt * 16 + g;
#pragma unroll
        for (int nt = 0; nt < 4; nt++) {
            int col = nBase + nt * 8 + t2;
            if (row0 < M) {
                __half2 p = __floats2half2_rn(acc[mt][nt][0], acc[mt][nt][1]);
                *(uint32_t*)(C + (size_t)row0 * NOUT + col) = *reinterpret_cast<uint32_t*>(&p);
            }
            if (row0 + 8 < M) {
                __half2 p = __floats2half2_rn(acc[mt][nt][2], acc[mt][nt][3]);
                *(uint32_t*)(C + (size_t)(row0 + 8) * NOUT + col) = *reinterpret_cast<uint32_t*>(&p);
            }
        }
    }
}

// ---------------- layer-1 aggregation (fp16 gather, fp32 accum) + bias + relu -> fp16 ----------------
__device__ __forceinline__ float4 ldh4(const __half* p) {
    uint2 raw = *(const uint2*)p;
    __half2 h0 = *reinterpret_cast<__half2*>(&raw.x);
    __half2 h1 = *reinterpret_cast<__half2*>(&raw.y);
    float2 f0 = __half22float2(h0);
    float2 f1 = __half22float2(h1);
    return make_float4(f0.x, f0.y, f1.x, f1.y);
}

__global__ __launch_bounds__(256) void k_agg1(const float* __restrict__ b1) {
    int warp = (blockIdx.x * blockDim.x + threadIdx.x) >> 5;
    if (warp >= N_NODES) return;
    int lane = threadIdx.x & 31;
    int beg = g_rowptr[warp], end = g_rowptr[warp + 1];
    const int off = lane << 2;
    float4 acc = make_float4(0.f, 0.f, 0.f, 0.f);
    int j = beg;
    for (; j + 4 <= end; j += 4) {
        int2 e0 = g_colnrm[j], e1 = g_colnrm[j + 1];
        int2 e2 = g_colnrm[j + 2], e3 = g_colnrm[j + 3];
        float4 h0 = ldh4(g_H1h + (size_t)e0.x * F1 + off);
        float4 h1 = ldh4(g_H1h + (size_t)e1.x * F1 + off);
        float4 h2 = ldh4(g_H1h + (size_t)e2.x * F1 + off);
        float4 h3 = ldh4(g_H1h + (size_t)e3.x * F1 + off);
        float w0 = __int_as_float(e0.y), w1 = __int_as_float(e1.y);
        float w2 = __int_as_float(e2.y), w3 = __int_as_float(e3.y);
        acc.x = fmaf(h0.x, w0, fmaf(h1.x, w1, fmaf(h2.x, w2, fmaf(h3.x, w3, acc.x))));
        acc.y = fmaf(h0.y, w0, fmaf(h1.y, w1, fmaf(h2.y, w2, fmaf(h3.y, w3, acc.y))));
        acc.z = fmaf(h0.z, w0, fmaf(h1.z, w1, fmaf(h2.z, w2, fmaf(h3.z, w3, acc.z))));
        acc.w = fmaf(h0.w, w0, fmaf(h1.w, w1, fmaf(h2.w, w2, fmaf(h3.w, w3, acc.w))));
    }
    for (; j < end; j++) {
        int2 e0 = g_colnrm[j];
        float w0 = __int_as_float(e0.y);
        float4 h0 = ldh4(g_H1h + (size_t)e0.x * F1 + off);
        acc.x = fmaf(h0.x, w0, acc.x);
        acc.y = fmaf(h0.y, w0, acc.y);
        acc.z = fmaf(h0.z, w0, acc.z);
        acc.w = fmaf(h0.w, w0, acc.w);
    }
    float4 bb = *(const float4*)(b1 + off);
    __half2 p0 = __floats2half2_rn(fmaxf(acc.x + bb.x, 0.f), fmaxf(acc.y + bb.y, 0.f));
    __half2 p1 = __floats2half2_rn(fmaxf(acc.z + bb.z, 0.f), fmaxf(acc.w + bb.w, 0.f));
    uint2 pk;
    pk.x = *reinterpret_cast<uint32_t*>(&p0);
    pk.y = *reinterpret_cast<uint32_t*>(&p1);
    *(uint2*)(g_A1h + (size_t)warp * F1 + off) = pk;
}

// ---------------- layer-2 aggregation (fp16 gather) + bias + softmax ----------------
__global__ __launch_bounds__(256) void k_agg2(const float* __restrict__ b2,
                                              float* __restrict__ out) {
    int warp = (blockIdx.x * blockDim.x + threadIdx.x) >> 5;
    if (warp >= N_NODES) return;
    int lane = threadIdx.x & 31;
    int beg = g_rowptr[warp], end = g_rowptr[warp + 1];
    const int off = lane << 1;
    float2 acc = make_float2(0.f, 0.f);
    int j = beg;
    for (; j + 4 <= end; j += 4) {
        int2 e0 = g_colnrm[j], e1 = g_colnrm[j + 1];
        int2 e2 = g_colnrm[j + 2], e3 = g_colnrm[j + 3];
        __half2 p0 = *(const __half2*)(g_H2h + (size_t)e0.x * F2 + off);
        __half2 p1 = *(const __half2*)(g_H2h + (size_t)e1.x * F2 + off);
        __half2 p2 = *(const __half2*)(g_H2h + (size_t)e2.x * F2 + off);
        __half2 p3 = *(const __half2*)(g_H2h + (size_t)e3.x * F2 + off);
        float2 h0 = __half22float2(p0), h1 = __half22float2(p1);
        float2 h2 = __half22float2(p2), h3 = __half22float2(p3);
        float w0 = __int_as_float(e0.y), w1 = __int_as_float(e1.y);
        float w2 = __int_as_float(e2.y), w3 = __int_as_float(e3.y);
        acc.x = fmaf(h0.x, w0, fmaf(h1.x, w1, fmaf(h2.x, w2, fmaf(h3.x, w3, acc.x))));
        acc.y = fmaf(h0.y, w0, fmaf(h1.y, w1, fmaf(h2.y, w2, fmaf(h3.y, w3, acc.y))));
    }
    for (; j < end; j++) {
        int2 e0 = g_colnrm[j];
        float w0 = __int_as_float(e0.y);
        float2 h0 = __half22float2(*(const __half2*)(g_H2h + (size_t)e0.x * F2 + off));
        acc.x = fmaf(h0.x, w0, acc.x);
        acc.y = fmaf(h0.y, w0, acc.y);
    }
    float2 bb = *(const float2*)(b2 + off);
    float l0 = acc.x + bb.x;
    float l1 = acc.y + bb.y;
    float m = fmaxf(l0, l1);
#pragma unroll
    for (int o = 16; o > 0; o >>= 1)
        m = fmaxf(m, __shfl_xor_sync(0xffffffffu, m, o));
    float e0 = __expf(l0 - m);
    float e1 = __expf(l1 - m);
    float s = e0 + e1;
#pragma unroll
    for (int o = 16; o > 0; o >>= 1)
        s += __shfl_xor_sync(0xffffffffu, s, o);
    float inv = 1.0f / s;
    *(float2*)(out + (size_t)warp * F2 + off) = make_float2(e0 * inv, e1 * inv);
}

// ---------------- launch ----------------
extern "C" void kernel_launch(void* const* d_in, const int* in_sizes, int n_in,
                              void* d_out, int out_size) {
    const float* x  = (const float*)d_in[0];
    const void*  ei = d_in[1];
    const float* W1 = (const float*)d_in[2];
    const float* b1 = (const float*)d_in[3];
    const float* W2 = (const float*)d_in[4];
    const float* b2 = (const float*)d_in[5];
    float* out = (float*)d_out;
    int E = in_sizes[1] / 2;

    __half *H1h, *A1h, *H2h;
    cudaGetSymbolAddress((void**)&H1h, g_H1h);
    cudaGetSymbolAddress((void**)&A1h, g_A1h);
    cudaGetSymbolAddress((void**)&H2h, g_H2h);

    const int nTiles = (N_NODES + 127) / 128;     // 391
    const int LDA = 136;
    const int SMEM1 = (128 + 128) * LDA * 2;      // 69632
    const int SMEM2 = (128 + 64) * LDA * 2;       // 52224
    cudaFuncSetAttribute((const void*)k_gemm_mma<128, 0>,
        cudaFuncAttributeMaxDynamicSharedMemorySize, SMEM1);
    cudaFuncSetAttribute((const void*)k_gemm_mma<64, 1>,
        cudaFuncAttributeMaxDynamicSharedMemorySize, SMEM2);

    k_init_detect<<<(N_NODES + 255) / 256, 256>>>(ei);
    k_degree<<<(E + 255) / 256, 256>>>(ei, E);
    k_scan<<<1, 1024>>>();
    k_scatter<<<(E + N_NODES + 255) / 256, 256>>>(ei, E);

    k_gemm_mma<128, 0><<<nTiles, 256, SMEM1>>>(x, W1, H1h, N_NODES);
    k_agg1<<<(N_NODES * 32 + 255) / 256, 256>>>(b1);
    k_gemm_mma<64, 1><<<nTiles, 256, SMEM2>>>(A1h, W2, H2h, N_NODES);
    k_agg2<<<(N_NODES * 32 + 255) / 256, 256>>>(b2, out);
}